// round 3
// baseline (speedup 1.0000x reference)
#include <cuda_runtime.h>
#include <cuda_fp16.h>
#include <mma.h>
#include <math.h>

using namespace nvcuda;

#define N_NODES 38332
#define N_PAD   38400            /* multiple of 64 for unguarded gemm epilogue */
#define POI_LEN_ 38333
#define POI_DIM 300
#define CAT_DIM 100
#define FEAT_DIM 403
#define CCH 128
#define NLAYERS 5
#define NEDGES 1200000
#define TOTE (NEDGES + N_NODES)
#define NEG 0.01f
#define GAT_NEG 0.2f

// ---------------- scratch (static __device__, no allocation) ----------------
__device__ float  d_feat[N_NODES * FEAT_DIM];
__device__ float  d_x [N_NODES * CCH];
__device__ __half d_xwh[N_PAD * CCH];     // fp16 projected features
__device__ float  d_y [N_NODES * CCH];
__device__ int    d_csr_src [TOTE];
__device__ float  d_csr_w   [TOTE];
__device__ float  d_csr_norm[TOTE];
__device__ int    d_row_ptr[N_NODES + 1];
__device__ int    d_cnt   [N_NODES];
__device__ int    d_cursor[N_NODES];
__device__ float  d_dinv[N_NODES];
__device__ float  d_al [N_NODES];
__device__ float  d_ar [N_NODES];
__device__ float  d_xw1[N_NODES];
__device__ float  d_xs [N_NODES];
__device__ float  d_stat[2 * CCH];
__device__ float  d_shift[CCH];
__device__ float  d_rstd [CCH];
__device__ float  d_hraw[CCH];
__device__ float  d_h   [CCH];

__device__ __forceinline__ float leaky01(float v) { return v > 0.f ? v : NEG * v; }
__device__ __forceinline__ float leaky20(float v) { return v > 0.f ? v : GAT_NEG * v; }

// ---------------- CSR build ----------------
__global__ void init_k() {
    int i = blockIdx.x * blockDim.x + threadIdx.x;
    if (i < N_NODES) d_cnt[i] = 1;                 // self-loop pre-counted
    if (i < CCH)     d_hraw[i] = 0.f;
    if (i < 2 * CCH) d_stat[i] = 0.f;
}

__global__ void hist_k(const int* __restrict__ ei) {
    int e = blockIdx.x * blockDim.x + threadIdx.x;
    if (e < NEDGES) atomicAdd(&d_cnt[ei[NEDGES + e]], 1);   // dst row
}

__global__ void scan_k() {
    const int T = 1024;
    const int ITEMS = (N_NODES + T - 1) / T;   // 38
    int tid = threadIdx.x;
    int start = tid * ITEMS;
    int end   = min(start + ITEMS, N_NODES);
    int s = 0;
    for (int i = start; i < end; i++) s += d_cnt[i];
    __shared__ int ps[T];
    ps[tid] = s; __syncthreads();
    for (int off = 1; off < T; off <<= 1) {
        int v = (tid >= off) ? ps[tid - off] : 0;
        __syncthreads();
        ps[tid] += v;
        __syncthreads();
    }
    int incl = ps[tid];
    int run  = incl - s;                        // exclusive prefix
    for (int i = start; i < end; i++) { d_row_ptr[i] = run; run += d_cnt[i]; }
    if (tid == T - 1) d_row_ptr[N_NODES] = incl;
}

__global__ void selfloop_k() {
    int i = blockIdx.x * blockDim.x + threadIdx.x;
    if (i < N_NODES) {
        int p = d_row_ptr[i];
        d_csr_src[p] = i;
        d_csr_w[p]   = 1.0f;
        d_cursor[i]  = p + 1;
    }
}

__global__ void scatter_k(const int* __restrict__ ei, const float* __restrict__ ew) {
    int e = blockIdx.x * blockDim.x + threadIdx.x;
    if (e < NEDGES) {
        int dst = ei[NEDGES + e];
        int p = atomicAdd(&d_cursor[dst], 1);
        d_csr_src[p] = ei[e];
        d_csr_w[p]   = ew[e];
    }
}

__global__ void deg_k() {
    int g = blockIdx.x * blockDim.x + threadIdx.x;
    int node = g >> 5, lane = g & 31;
    if (node >= N_NODES) return;
    int s = d_row_ptr[node], e = d_row_ptr[node + 1];
    float acc = 0.f;
    for (int j = s + lane; j < e; j += 32) acc += d_csr_w[j];
    #pragma unroll
    for (int off = 16; off; off >>= 1) acc += __shfl_down_sync(0xffffffffu, acc, off);
    if (lane == 0) d_dinv[node] = rsqrtf(acc);   // deg >= 1 (self-loop)
}

__global__ void csnorm_k() {
    int g = blockIdx.x * blockDim.x + threadIdx.x;
    int node = g >> 5, lane = g & 31;
    if (node >= N_NODES) return;
    int s = d_row_ptr[node], e = d_row_ptr[node + 1];
    float dv = d_dinv[node];
    for (int j = s + lane; j < e; j += 32)
        d_csr_norm[j] = d_dinv[d_csr_src[j]] * d_csr_w[j] * dv;
}

// ---------------- feature assembly ----------------
__global__ void feat_k(const int* __restrict__ poi_ids, const int* __restrict__ cat_ids,
                       const float* __restrict__ feat3,
                       const float* __restrict__ poi_emb, const float* __restrict__ cat_emb) {
    int node = blockIdx.x, tid = threadIdx.x;
    int pid = poi_ids[node], cid = cat_ids[node];
    float* f = d_feat + (long)node * FEAT_DIM;
    for (int k = tid; k < POI_DIM; k += 128) f[k] = poi_emb[(long)pid * POI_DIM + k];
    for (int k = tid; k < CAT_DIM; k += 128) f[POI_DIM + k] = cat_emb[cid * CAT_DIM + k];
    if (tid < 3) f[400 + tid] = feat3[node * 3 + tid];
}

// ---------------- fused GEMM (tf32) : Yh[n,128] = op(X)[n,K] @ W[K,128] --------------
// fuse_norm: X element = xio + leaky01(gamma*(yin-shift)*rstd + beta), written back to xio (K=128)
// fuse_alar: epilogue also computes d_al/d_ar row dots with asrc/adst (fp32 accumulators)
// epilogue: fp32 accum -> smem -> fp16 Yh
#define GM 64
#define GN 128
#define GK 16
#define CS_LD (GN + 4)

__global__ __launch_bounds__(256) void gemm_tf32_v2(
    const float* __restrict__ X, const float* __restrict__ Wm, __half* __restrict__ Yh,
    int n, int K,
    const float* __restrict__ yin, float* __restrict__ xio,
    const float* __restrict__ gamma, const float* __restrict__ beta, int fuse_norm,
    const float* __restrict__ asrc, const float* __restrict__ adst, int fuse_alar) {
    __shared__ __align__(16) float Xs[GM][GK];
    __shared__ __align__(16) float Ws[GK][GN];
    __shared__ __align__(16) float Cs[GM][CS_LD];
    __shared__ float gS[CCH], bS[CCH], shS[CCH], rsS[CCH], asS[CCH], adS[CCH];

    int tid = threadIdx.x;
    int warp = tid >> 5;
    int wm = warp & 1, wn = warp >> 1;
    int row0 = blockIdx.x * GM;

    if (fuse_norm && tid < CCH) {
        gS[tid] = gamma[tid]; bS[tid] = beta[tid];
        shS[tid] = d_shift[tid]; rsS[tid] = d_rstd[tid];
    }
    if (fuse_alar && tid < CCH) { asS[tid] = asrc[tid]; adS[tid] = adst[tid]; }
    __syncthreads();

    wmma::fragment<wmma::accumulator, 16, 16, 8, float> c[2][2];
    #pragma unroll
    for (int i = 0; i < 2; i++)
        #pragma unroll
        for (int j = 0; j < 2; j++) wmma::fill_fragment(c[i][j], 0.f);

    for (int k0 = 0; k0 < K; k0 += GK) {
        #pragma unroll
        for (int i = 0; i < 4; i++) {
            int e = tid + i * 256;
            int r = e >> 4, kk = e & 15;
            int gr = row0 + r, gk = k0 + kk;
            float v = 0.f;
            if (gr < n) {
                if (fuse_norm) {   // K == 128 here
                    size_t off = (size_t)gr * CCH + gk;
                    float t = gS[gk] * (yin[off] - shS[gk]) * rsS[gk] + bS[gk];
                    v = xio[off] + leaky01(t);
                    xio[off] = v;
                } else if (gk < K) {
                    v = X[(size_t)gr * K + gk];
                }
            }
            Xs[r][kk] = v;
        }
        #pragma unroll
        for (int i = 0; i < 2; i++) {
            int e = tid + i * 256;               // float4 slot in [0,512)
            int kk = e >> 5, c4 = e & 31;
            int gk = k0 + kk;
            float4 v = (gk < K) ? ((const float4*)(Wm + (size_t)gk * GN))[c4]
                                : make_float4(0.f, 0.f, 0.f, 0.f);
            ((float4*)&Ws[kk][0])[c4] = v;
        }
        __syncthreads();
        #pragma unroll
        for (int ks = 0; ks < 2; ks++) {
            wmma::fragment<wmma::matrix_a, 16, 16, 8, wmma::precision::tf32, wmma::row_major> a[2];
            wmma::fragment<wmma::matrix_b, 16, 16, 8, wmma::precision::tf32, wmma::row_major> bf[2];
            #pragma unroll
            for (int i = 0; i < 2; i++) {
                wmma::load_matrix_sync(a[i], &Xs[wm * 32 + i * 16][ks * 8], GK);
                #pragma unroll
                for (int t = 0; t < a[i].num_elements; t++)
                    a[i].x[t] = wmma::__float_to_tf32(a[i].x[t]);
            }
            #pragma unroll
            for (int j = 0; j < 2; j++) {
                wmma::load_matrix_sync(bf[j], &Ws[ks * 8][wn * 32 + j * 16], GN);
                #pragma unroll
                for (int t = 0; t < bf[j].num_elements; t++)
                    bf[j].x[t] = wmma::__float_to_tf32(bf[j].x[t]);
            }
            #pragma unroll
            for (int i = 0; i < 2; i++)
                #pragma unroll
                for (int j = 0; j < 2; j++)
                    wmma::mma_sync(c[i][j], a[i], bf[j], c[i][j]);
        }
        __syncthreads();
    }

    // epilogue: accum -> smem
    #pragma unroll
    for (int i = 0; i < 2; i++)
        #pragma unroll
        for (int j = 0; j < 2; j++)
            wmma::store_matrix_sync(&Cs[wm * 32 + i * 16][wn * 32 + j * 16],
                                    c[i][j], CS_LD, wmma::mem_row_major);
    __syncthreads();

    // smem -> fp16 gmem (+ optional al/ar row dots)
    int r = tid >> 2, cq = tid & 3;
    int c0 = cq * 32;
    int gr = row0 + r;                      // grid sized to N_PAD: always in-bounds for Yh
    float al = 0.f, ar = 0.f;
    uint2 tmp[8];
    #pragma unroll
    for (int i4 = 0; i4 < 8; i4++) {
        float4 vv = *(const float4*)&Cs[r][c0 + i4 * 4];
        if (fuse_alar) {
            int cc = c0 + i4 * 4;
            al += vv.x * asS[cc] + vv.y * asS[cc + 1] + vv.z * asS[cc + 2] + vv.w * asS[cc + 3];
            ar += vv.x * adS[cc] + vv.y * adS[cc + 1] + vv.z * adS[cc + 2] + vv.w * adS[cc + 3];
        }
        __half2 h0 = __floats2half2_rn(vv.x, vv.y);
        __half2 h1 = __floats2half2_rn(vv.z, vv.w);
        tmp[i4] = make_uint2(*(unsigned*)&h0, *(unsigned*)&h1);
    }
    uint4* dst = (uint4*)(Yh + (size_t)gr * CCH + c0);
    dst[0] = make_uint4(tmp[0].x, tmp[0].y, tmp[1].x, tmp[1].y);
    dst[1] = make_uint4(tmp[2].x, tmp[2].y, tmp[3].x, tmp[3].y);
    dst[2] = make_uint4(tmp[4].x, tmp[4].y, tmp[5].x, tmp[5].y);
    dst[3] = make_uint4(tmp[6].x, tmp[6].y, tmp[7].x, tmp[7].y);
    if (fuse_alar) {
        al += __shfl_down_sync(0xffffffffu, al, 2, 4);
        al += __shfl_down_sync(0xffffffffu, al, 1, 4);
        ar += __shfl_down_sync(0xffffffffu, ar, 2, 4);
        ar += __shfl_down_sync(0xffffffffu, ar, 1, 4);
        if (cq == 0 && gr < n) { d_al[gr] = al; d_ar[gr] = ar; }
    }
}

// ---------------- GCN aggregation: warp per node, fp16 gather, fused stats --------------
__global__ __launch_bounds__(256) void gcn_agg_h(const __half* __restrict__ xwh,
                                                 const float* __restrict__ b,
                                                 float* __restrict__ y,
                                                 int do_leaky, int do_stats) {
    int w = threadIdx.x >> 5, lane = threadIdx.x & 31;
    int node = blockIdx.x * 8 + w;
    float4 acc = make_float4(0.f, 0.f, 0.f, 0.f);
    if (node < N_NODES) {
        int s = d_row_ptr[node], e = d_row_ptr[node + 1];
        for (int base = s; base < e; base += 32) {
            int j = base + lane;
            int srcL = 0; float nrmL = 0.f;
            if (j < e) { srcL = d_csr_src[j]; nrmL = d_csr_norm[j]; }
            int cnt = min(32, e - base);
            for (int q = 0; q < cnt; q++) {
                int   sq = __shfl_sync(0xffffffffu, srcL, q);
                float nq = __shfl_sync(0xffffffffu, nrmL, q);
                uint2 v = ((const uint2*)(xwh + (size_t)sq * CCH))[lane];
                float2 f01 = __half22float2(*(__half2*)&v.x);
                float2 f23 = __half22float2(*(__half2*)&v.y);
                acc.x += nq * f01.x; acc.y += nq * f01.y;
                acc.z += nq * f23.x; acc.w += nq * f23.y;
            }
        }
        float4 bb = ((const float4*)b)[lane];
        acc.x += bb.x; acc.y += bb.y; acc.z += bb.z; acc.w += bb.w;
        if (do_leaky) {
            acc.x = leaky01(acc.x); acc.y = leaky01(acc.y);
            acc.z = leaky01(acc.z); acc.w = leaky01(acc.w);
        }
        ((float4*)(y + (size_t)node * CCH))[lane] = acc;
    }
    if (do_stats) {
        __shared__ float4 ssum[8][32], ssq[8][32];
        ssum[w][lane] = acc;
        ssq[w][lane]  = make_float4(acc.x * acc.x, acc.y * acc.y, acc.z * acc.z, acc.w * acc.w);
        __syncthreads();
        if (w == 0) {
            float4 s = ssum[0][lane], q = ssq[0][lane];
            #pragma unroll
            for (int i = 1; i < 8; i++) {
                float4 a = ssum[i][lane], p = ssq[i][lane];
                s.x += a.x; s.y += a.y; s.z += a.z; s.w += a.w;
                q.x += p.x; q.y += p.y; q.z += p.z; q.w += p.w;
            }
            int c = lane * 4;
            atomicAdd(&d_stat[c + 0], s.x); atomicAdd(&d_stat[c + 1], s.y);
            atomicAdd(&d_stat[c + 2], s.z); atomicAdd(&d_stat[c + 3], s.w);
            atomicAdd(&d_stat[CCH + c + 0], q.x); atomicAdd(&d_stat[CCH + c + 1], q.y);
            atomicAdd(&d_stat[CCH + c + 2], q.z); atomicAdd(&d_stat[CCH + c + 3], q.w);
        }
    }
}

// ---------------- GAT aggregation: warp per node, fp16 gather, fused stats --------------
__global__ __launch_bounds__(256) void gat_agg_h(const __half* __restrict__ xwh,
                                                 const float* __restrict__ b,
                                                 float* __restrict__ y) {
    int w = threadIdx.x >> 5, lane = threadIdx.x & 31;
    int node = blockIdx.x * 8 + w;
    float4 acc = make_float4(0.f, 0.f, 0.f, 0.f);
    if (node < N_NODES) {
        int s = d_row_ptr[node], e = d_row_ptr[node + 1];
        float arn = d_ar[node];

        float m = -1e30f;
        for (int j = s + lane; j < e; j += 32)
            m = fmaxf(m, leaky20(d_al[d_csr_src[j]] + arn));
        #pragma unroll
        for (int off = 16; off; off >>= 1) m = fmaxf(m, __shfl_xor_sync(0xffffffffu, m, off));

        float sm = 0.f;
        for (int j = s + lane; j < e; j += 32)
            sm += __expf(leaky20(d_al[d_csr_src[j]] + arn) - m);
        #pragma unroll
        for (int off = 16; off; off >>= 1) sm += __shfl_xor_sync(0xffffffffu, sm, off);
        float inv = 1.f / sm;

        for (int base = s; base < e; base += 32) {
            int j = base + lane;
            int srcL = 0; float attL = 0.f;
            if (j < e) {
                srcL = d_csr_src[j];
                attL = __expf(leaky20(d_al[srcL] + arn) - m) * inv;
            }
            int cnt = min(32, e - base);
            for (int q = 0; q < cnt; q++) {
                int   sq = __shfl_sync(0xffffffffu, srcL, q);
                float aq = __shfl_sync(0xffffffffu, attL, q);
                uint2 v = ((const uint2*)(xwh + (size_t)sq * CCH))[lane];
                float2 f01 = __half22float2(*(__half2*)&v.x);
                float2 f23 = __half22float2(*(__half2*)&v.y);
                acc.x += aq * f01.x; acc.y += aq * f01.y;
                acc.z += aq * f23.x; acc.w += aq * f23.y;
            }
        }
        float4 bb = ((const float4*)b)[lane];
        acc.x += bb.x; acc.y += bb.y; acc.z += bb.z; acc.w += bb.w;
        ((float4*)(y + (size_t)node * CCH))[lane] = acc;
    }
    // fused GraphNorm stats
    __shared__ float4 ssum[8][32], ssq[8][32];
    ssum[w][lane] = acc;
    ssq[w][lane]  = make_float4(acc.x * acc.x, acc.y * acc.y, acc.z * acc.z, acc.w * acc.w);
    __syncthreads();
    if (w == 0) {
        float4 s = ssum[0][lane], q = ssq[0][lane];
        #pragma unroll
        for (int i = 1; i < 8; i++) {
            float4 a = ssum[i][lane], p = ssq[i][lane];
            s.x += a.x; s.y += a.y; s.z += a.z; s.w += a.w;
            q.x += p.x; q.y += p.y; q.z += p.z; q.w += p.w;
        }
        int c = lane * 4;
        atomicAdd(&d_stat[c + 0], s.x); atomicAdd(&d_stat[c + 1], s.y);
        atomicAdd(&d_stat[c + 2], s.z); atomicAdd(&d_stat[c + 3], s.w);
        atomicAdd(&d_stat[CCH + c + 0], q.x); atomicAdd(&d_stat[CCH + c + 1], q.y);
        atomicAdd(&d_stat[CCH + c + 2], q.z); atomicAdd(&d_stat[CCH + c + 3], q.w);
    }
}

// ---------------- GraphNorm finalize ----------------
__global__ void norm_final(const float* __restrict__ alpha) {
    int c = threadIdx.x;
    float m = d_stat[c] * (1.0f / N_NODES);
    float q = d_stat[CCH + c] * (1.0f / N_NODES);
    float a = alpha[c];
    float var = q - (2.f * a - a * a) * m * m;   // E[(y - a*mean)^2]
    d_shift[c] = a * m;
    d_rstd[c]  = rsqrtf(var + 1e-5f);
    d_stat[c] = 0.f;            // reset for next layer
    d_stat[CCH + c] = 0.f;
}

// ---------------- output head ----------------
// fused: final norm_apply (no write-back needed) + dot with Wout
__global__ void gemv_out_f(const float* __restrict__ x, const float* __restrict__ yin,
                           const float* __restrict__ gamma, const float* __restrict__ beta,
                           const float* __restrict__ Wout) {
    int g = blockIdx.x * blockDim.x + threadIdx.x;
    int node = g >> 5, lane = g & 31;
    if (node >= N_NODES) return;
    float4 xv = ((const float4*)(x + (size_t)node * CCH))[lane];
    float4 yv = ((const float4*)(yin + (size_t)node * CCH))[lane];
    float4 gm = ((const float4*)gamma)[lane];
    float4 bt = ((const float4*)beta)[lane];
    float4 sh = ((const float4*)d_shift)[lane];
    float4 rs = ((const float4*)d_rstd)[lane];
    float4 w  = ((const float4*)Wout)[lane];
    float vx = xv.x + leaky01(gm.x * (yv.x - sh.x) * rs.x + bt.x);
    float vy = xv.y + leaky01(gm.y * (yv.y - sh.y) * rs.y + bt.y);
    float vz = xv.z + leaky01(gm.z * (yv.z - sh.z) * rs.z + bt.z);
    float vw = xv.w + leaky01(gm.w * (yv.w - sh.w) * rs.w + bt.w);
    float d = vx * w.x + vy * w.y + vz * w.z + vw * w.w;
    #pragma unroll
    for (int off = 16; off; off >>= 1) d += __shfl_down_sync(0xffffffffu, d, off);
    if (lane == 0) d_xw1[node] = d;
}

__global__ void scalar_agg(const float* __restrict__ b_out) {
    int g = blockIdx.x * blockDim.x + threadIdx.x;
    int node = g >> 5, lane = g & 31;
    if (node >= N_NODES) return;
    int s = d_row_ptr[node], e = d_row_ptr[node + 1];
    float acc = 0.f;
    for (int j = s + lane; j < e; j += 32)
        acc += d_csr_norm[j] * d_xw1[d_csr_src[j]];
    #pragma unroll
    for (int off = 16; off; off >>= 1) acc += __shfl_down_sync(0xffffffffu, acc, off);
    if (lane == 0) d_xs[node] = leaky01(acc + b_out[0]);
}

__global__ void fc1_partial(const float* __restrict__ W1) {
    int c = threadIdx.x;
    float acc = 0.f;
    for (int n = blockIdx.x; n < N_NODES; n += gridDim.x)
        acc += d_xs[n] * W1[(size_t)n * CCH + c];
    atomicAdd(&d_hraw[c], acc);
}

__global__ void fc1_final(const float* __restrict__ b1) {
    int c = threadIdx.x;
    float v = d_hraw[c] + b1[c];
    d_h[c] = v > 0.f ? v : 0.f;
}

__global__ void fc2_k(const float* __restrict__ W2, const float* __restrict__ b2,
                      float* __restrict__ out) {
    __shared__ float hs[CCH];
    int tid = threadIdx.x;
    hs[tid] = d_h[tid];
    __syncthreads();
    int p = blockIdx.x * 128 + tid;
    if (p >= POI_LEN_) return;
    float acc = b2[p];
    #pragma unroll 8
    for (int j = 0; j < CCH; j++)
        acc += hs[j] * W2[(size_t)j * POI_LEN_ + p];
    out[p] = acc > 0.f ? acc : 0.f;
}

// ---------------- launch ----------------
static inline int div_up(int a, int b) { return (a + b - 1) / b; }

extern "C" void kernel_launch(void* const* d_in, const int* in_sizes, int n_in,
                              void* d_out, int out_size) {
    const int*   poi_ids   = (const int*)  d_in[0];
    const int*   cat_ids   = (const int*)  d_in[1];
    const float* feat3     = (const float*)d_in[2];
    const int*   edge_index= (const int*)  d_in[3];
    const float* edge_w    = (const float*)d_in[4];
    const float* poi_emb   = (const float*)d_in[5];
    const float* cat_emb   = (const float*)d_in[6];
    const float* Win       = (const float*)d_in[7];
    const float* b_in      = (const float*)d_in[8];
    const float* gcn_W     = (const float*)d_in[9];
    const float* gcn_b     = (const float*)d_in[10];
    const float* gn_gamma  = (const float*)d_in[11];
    const float* gn_beta   = (const float*)d_in[12];
    const float* gn_alpha  = (const float*)d_in[13];
    const float* gat_W     = (const float*)d_in[14];
    const float* gat_asrc  = (const float*)d_in[15];
    const float* gat_adst  = (const float*)d_in[16];
    const float* gat_b     = (const float*)d_in[17];
    const float* Wout      = (const float*)d_in[18];
    const float* b_out     = (const float*)d_in[19];
    const float* fc_W1     = (const float*)d_in[20];
    const float* fc_b1     = (const float*)d_in[21];
    const float* fc_W2     = (const float*)d_in[22];
    const float* fc_b2     = (const float*)d_in[23];
    float* out = (float*)d_out;

    float *feat_p, *x_p, *y_p; __half *xwh_p;
    cudaGetSymbolAddress((void**)&feat_p, d_feat);
    cudaGetSymbolAddress((void**)&x_p,  d_x);
    cudaGetSymbolAddress((void**)&y_p,  d_y);
    cudaGetSymbolAddress((void**)&xwh_p, d_xwh);

    const int warpGrid = div_up(N_NODES * 32, 256);
    const int edgeGrid = div_up(NEDGES, 256);
    const int gemmGrid = N_PAD / GM;             // 600
    const int aggGrid  = div_up(N_NODES, 8);

    // CSR build
    init_k<<<div_up(N_NODES, 256), 256>>>();
    hist_k<<<edgeGrid, 256>>>(edge_index);
    scan_k<<<1, 1024>>>();
    selfloop_k<<<div_up(N_NODES, 256), 256>>>();
    scatter_k<<<edgeGrid, 256>>>(edge_index, edge_w);
    deg_k<<<warpGrid, 256>>>();
    csnorm_k<<<warpGrid, 256>>>();

    // features + input conv
    feat_k<<<N_NODES, 128>>>(poi_ids, cat_ids, feat3, poi_emb, cat_emb);
    gemm_tf32_v2<<<gemmGrid, 256>>>(feat_p, Win, xwh_p, N_NODES, FEAT_DIM,
                                    nullptr, nullptr, nullptr, nullptr, 0,
                                    nullptr, nullptr, 0);
    gcn_agg_h<<<aggGrid, 256>>>(xwh_p, b_in, x_p, 1, 0);

    for (int l = 0; l < NLAYERS; l++) {
        // GCN half: gemm (with previous GAT norm fused for l>0), agg + stats, finalize
        if (l == 0)
            gemm_tf32_v2<<<gemmGrid, 256>>>(x_p, gcn_W, xwh_p, N_NODES, CCH,
                                            nullptr, nullptr, nullptr, nullptr, 0,
                                            nullptr, nullptr, 0);
        else
            gemm_tf32_v2<<<gemmGrid, 256>>>(nullptr, gcn_W + l * CCH * CCH, xwh_p, N_NODES, CCH,
                                            y_p, x_p,
                                            gn_gamma + (l - 1) * CCH, gn_beta + (l - 1) * CCH, 1,
                                            nullptr, nullptr, 0);
        gcn_agg_h<<<aggGrid, 256>>>(xwh_p, gcn_b + l * CCH, y_p, 0, 1);
        norm_final<<<1, 128>>>(gn_alpha + l * CCH);

        // GAT half: gemm with fused GCN-norm + alar epilogue, agg + stats, finalize
        gemm_tf32_v2<<<gemmGrid, 256>>>(nullptr, gat_W + l * CCH * CCH, xwh_p, N_NODES, CCH,
                                        y_p, x_p,
                                        gn_gamma + l * CCH, gn_beta + l * CCH, 1,
                                        gat_asrc + l * CCH, gat_adst + l * CCH, 1);
        gat_agg_h<<<aggGrid, 256>>>(xwh_p, gat_b + l * CCH, y_p);
        norm_final<<<1, 128>>>(gn_alpha + l * CCH);
    }

    // output conv (final norm fused) + FC head
    gemv_out_f<<<warpGrid, 256>>>(x_p, y_p, gn_gamma + 4 * CCH, gn_beta + 4 * CCH, Wout);
    scalar_agg<<<warpGrid, 256>>>(b_out);
    fc1_partial<<<592, 128>>>(fc_W1);
    fc1_final<<<1, 128>>>(fc_b1);
    fc2_k<<<div_up(POI_LEN_, 128), 128>>>(fc_W2, fc_b2, out);
}

// round 4
// speedup vs baseline: 1.0269x; 1.0269x over previous
#include <cuda_runtime.h>
#include <cuda_fp16.h>
#include <mma.h>
#include <math.h>

using namespace nvcuda;

#define N_NODES 38332
#define N_PAD   38400            /* multiple of 64 for unguarded gemm epilogue */
#define POI_LEN_ 38333
#define POI_DIM 300
#define CAT_DIM 100
#define FEAT_DIM 403
#define CCH 128
#define NLAYERS 5
#define NEDGES 1200000
#define TOTE (NEDGES + N_NODES)
#define NEG 0.01f
#define GAT_NEG 0.2f

// ---------------- scratch (static __device__, no allocation) ----------------
__device__ float  d_feat[N_NODES * FEAT_DIM];
__device__ float  d_x [N_NODES * CCH];
__device__ __half d_xwh[N_PAD * CCH];     // fp16 projected features
__device__ float  d_y [N_NODES * CCH];
__device__ int    d_csr_src [TOTE];
__device__ float  d_csr_w   [TOTE];
__device__ float  d_csr_norm[TOTE];
__device__ int    d_row_ptr[N_NODES + 1];
__device__ int    d_cnt   [N_NODES];
__device__ int    d_cursor[N_NODES];
__device__ float  d_dinv[N_NODES];
__device__ float  d_al [N_NODES];
__device__ float  d_ar [N_NODES];
__device__ float  d_xw1[N_NODES];
__device__ float  d_xs [N_NODES];
__device__ float  d_stat[2 * CCH];
__device__ float  d_shift[CCH];
__device__ float  d_rstd [CCH];
__device__ float  d_hraw[CCH];
__device__ float  d_h   [CCH];

__device__ __forceinline__ float leaky01(float v) { return v > 0.f ? v : NEG * v; }
__device__ __forceinline__ float leaky20(float v) { return v > 0.f ? v : GAT_NEG * v; }

// ---------------- CSR build ----------------
__global__ void init_k() {
    int i = blockIdx.x * blockDim.x + threadIdx.x;
    if (i < N_NODES) d_cnt[i] = 1;                 // self-loop pre-counted
    if (i < CCH)     d_hraw[i] = 0.f;
    if (i < 2 * CCH) d_stat[i] = 0.f;
}

__global__ void hist_k(const int* __restrict__ ei) {
    int e = blockIdx.x * blockDim.x + threadIdx.x;
    if (e < NEDGES) atomicAdd(&d_cnt[ei[NEDGES + e]], 1);   // dst row
}

__global__ void scan_k() {
    const int T = 1024;
    const int ITEMS = (N_NODES + T - 1) / T;   // 38
    int tid = threadIdx.x;
    int start = tid * ITEMS;
    int end   = min(start + ITEMS, N_NODES);
    int s = 0;
    for (int i = start; i < end; i++) s += d_cnt[i];
    __shared__ int ps[T];
    ps[tid] = s; __syncthreads();
    for (int off = 1; off < T; off <<= 1) {
        int v = (tid >= off) ? ps[tid - off] : 0;
        __syncthreads();
        ps[tid] += v;
        __syncthreads();
    }
    int incl = ps[tid];
    int run  = incl - s;                        // exclusive prefix
    for (int i = start; i < end; i++) { d_row_ptr[i] = run; run += d_cnt[i]; }
    if (tid == T - 1) d_row_ptr[N_NODES] = incl;
}

__global__ void selfloop_k() {
    int i = blockIdx.x * blockDim.x + threadIdx.x;
    if (i < N_NODES) {
        int p = d_row_ptr[i];
        d_csr_src[p] = i;
        d_csr_w[p]   = 1.0f;
        d_cursor[i]  = p + 1;
    }
}

__global__ void scatter_k(const int* __restrict__ ei, const float* __restrict__ ew) {
    int e = blockIdx.x * blockDim.x + threadIdx.x;
    if (e < NEDGES) {
        int dst = ei[NEDGES + e];
        int p = atomicAdd(&d_cursor[dst], 1);
        d_csr_src[p] = ei[e];
        d_csr_w[p]   = ew[e];
    }
}

__global__ void deg_k() {
    int g = blockIdx.x * blockDim.x + threadIdx.x;
    int node = g >> 5, lane = g & 31;
    if (node >= N_NODES) return;
    int s = d_row_ptr[node], e = d_row_ptr[node + 1];
    float acc = 0.f;
    for (int j = s + lane; j < e; j += 32) acc += d_csr_w[j];
    #pragma unroll
    for (int off = 16; off; off >>= 1) acc += __shfl_down_sync(0xffffffffu, acc, off);
    if (lane == 0) d_dinv[node] = rsqrtf(acc);   // deg >= 1 (self-loop)
}

__global__ void csnorm_k() {
    int g = blockIdx.x * blockDim.x + threadIdx.x;
    int node = g >> 5, lane = g & 31;
    if (node >= N_NODES) return;
    int s = d_row_ptr[node], e = d_row_ptr[node + 1];
    float dv = d_dinv[node];
    for (int j = s + lane; j < e; j += 32)
        d_csr_norm[j] = d_dinv[d_csr_src[j]] * d_csr_w[j] * dv;
}

// ---------------- feature assembly ----------------
__global__ void feat_k(const int* __restrict__ poi_ids, const int* __restrict__ cat_ids,
                       const float* __restrict__ feat3,
                       const float* __restrict__ poi_emb, const float* __restrict__ cat_emb) {
    int node = blockIdx.x, tid = threadIdx.x;
    int pid = poi_ids[node], cid = cat_ids[node];
    float* f = d_feat + (long)node * FEAT_DIM;
    for (int k = tid; k < POI_DIM; k += 128) f[k] = poi_emb[(long)pid * POI_DIM + k];
    for (int k = tid; k < CAT_DIM; k += 128) f[POI_DIM + k] = cat_emb[cid * CAT_DIM + k];
    if (tid < 3) f[400 + tid] = feat3[node * 3 + tid];
}

// ---------------- fused GEMM (tf32) : Yh[n,128] = op(X)[n,K] @ W[K,128] --------------
// fuse_norm: X element = xio + leaky01(gamma*(yin-shift)*rstd + beta), written back to xio
// fuse_alar: epilogue also computes d_al/d_ar row dots with asrc/adst (fp32 accumulators)
// Epilogue staged through REUSED Xs/Ws smem (4 passes of 16 rows) -> low smem, high occ.
#define GM 64
#define GN 128
#define GK 16
#define EPI_LD 132

__global__ __launch_bounds__(256) void gemm_tf32_v3(
    const float* __restrict__ X, const float* __restrict__ Wm, __half* __restrict__ Yh,
    int n, int K,
    const float* __restrict__ yin, float* __restrict__ xio,
    const float* __restrict__ gamma, const float* __restrict__ beta, int fuse_norm,
    const float* __restrict__ asrc, const float* __restrict__ adst, int fuse_alar) {
    // 12 KB main buffer: Xs[64][16] + Ws[16][128]; reused as Epi[16][132] (8.4KB) in epilogue
    __shared__ __align__(16) char smem_raw[(GM * GK + GK * GN) * 4];
    float (*Xs)[GK] = reinterpret_cast<float (*)[GK]>(smem_raw);
    float (*Ws)[GN] = reinterpret_cast<float (*)[GN]>(smem_raw + GM * GK * 4);
    float (*Epi)[EPI_LD] = reinterpret_cast<float (*)[EPI_LD]>(smem_raw);
    __shared__ float gS[CCH], bS[CCH], shS[CCH], rsS[CCH], asS[CCH], adS[CCH];

    int tid = threadIdx.x;
    int warp = tid >> 5;
    int wm = warp & 1, wn = warp >> 1;
    int row0 = blockIdx.x * GM;

    if (fuse_norm && tid < CCH) {
        gS[tid] = gamma[tid]; bS[tid] = beta[tid];
        shS[tid] = d_shift[tid]; rsS[tid] = d_rstd[tid];
    }
    if (fuse_alar && tid < CCH) { asS[tid] = asrc[tid]; adS[tid] = adst[tid]; }
    __syncthreads();

    wmma::fragment<wmma::accumulator, 16, 16, 8, float> c[2][2];
    #pragma unroll
    for (int i = 0; i < 2; i++)
        #pragma unroll
        for (int j = 0; j < 2; j++) wmma::fill_fragment(c[i][j], 0.f);

    for (int k0 = 0; k0 < K; k0 += GK) {
        #pragma unroll
        for (int i = 0; i < 4; i++) {
            int e = tid + i * 256;
            int r = e >> 4, kk = e & 15;
            int gr = row0 + r, gk = k0 + kk;
            float v = 0.f;
            if (gr < n) {
                if (fuse_norm) {   // K == 128 here
                    size_t off = (size_t)gr * CCH + gk;
                    float t = gS[gk] * (yin[off] - shS[gk]) * rsS[gk] + bS[gk];
                    v = xio[off] + leaky01(t);
                    xio[off] = v;
                } else if (gk < K) {
                    v = X[(size_t)gr * K + gk];
                }
            }
            Xs[r][kk] = v;
        }
        #pragma unroll
        for (int i = 0; i < 2; i++) {
            int e = tid + i * 256;               // float4 slot in [0,512)
            int kk = e >> 5, c4 = e & 31;
            int gk = k0 + kk;
            float4 v = (gk < K) ? ((const float4*)(Wm + (size_t)gk * GN))[c4]
                                : make_float4(0.f, 0.f, 0.f, 0.f);
            ((float4*)&Ws[kk][0])[c4] = v;
        }
        __syncthreads();
        #pragma unroll
        for (int ks = 0; ks < 2; ks++) {
            wmma::fragment<wmma::matrix_a, 16, 16, 8, wmma::precision::tf32, wmma::row_major> a[2];
            wmma::fragment<wmma::matrix_b, 16, 16, 8, wmma::precision::tf32, wmma::row_major> bf[2];
            #pragma unroll
            for (int i = 0; i < 2; i++) {
                wmma::load_matrix_sync(a[i], &Xs[wm * 32 + i * 16][ks * 8], GK);
                #pragma unroll
                for (int t = 0; t < a[i].num_elements; t++)
                    a[i].x[t] = wmma::__float_to_tf32(a[i].x[t]);
            }
            #pragma unroll
            for (int j = 0; j < 2; j++) {
                wmma::load_matrix_sync(bf[j], &Ws[ks * 8][wn * 32 + j * 16], GN);
                #pragma unroll
                for (int t = 0; t < bf[j].num_elements; t++)
                    bf[j].x[t] = wmma::__float_to_tf32(bf[j].x[t]);
            }
            #pragma unroll
            for (int i = 0; i < 2; i++)
                #pragma unroll
                for (int j = 0; j < 2; j++)
                    wmma::mma_sync(c[i][j], a[i], bf[j], c[i][j]);
        }
        __syncthreads();
    }

    // ---- epilogue: 4 passes of 16 rows through reused smem ----
    int rhalf = tid >> 4;        // 0..15 : local row
    int lane16 = tid & 15;       // 0..15 : 8-col group
    #pragma unroll
    for (int p = 0; p < 4; p++) {
        // pass p covers global rows row0 + p*16 .. +15 (owned by warps with wm == p>>1, i == p&1)
        if (wm == (p >> 1)) {
            int i = p & 1;
            wmma::store_matrix_sync(&Epi[0][wn * 32],      c[i][0], EPI_LD, wmma::mem_row_major);
            wmma::store_matrix_sync(&Epi[0][wn * 32 + 16], c[i][1], EPI_LD, wmma::mem_row_major);
        }
        __syncthreads();
        int grow = row0 + p * 16 + rhalf;
        int c0 = lane16 * 8;
        float4 v0 = *(const float4*)&Epi[rhalf][c0];
        float4 v1 = *(const float4*)&Epi[rhalf][c0 + 4];
        __half2 h0 = __floats2half2_rn(v0.x, v0.y);
        __half2 h1 = __floats2half2_rn(v0.z, v0.w);
        __half2 h2 = __floats2half2_rn(v1.x, v1.y);
        __half2 h3 = __floats2half2_rn(v1.z, v1.w);
        *(uint4*)(Yh + (size_t)grow * CCH + c0) =
            make_uint4(*(unsigned*)&h0, *(unsigned*)&h1, *(unsigned*)&h2, *(unsigned*)&h3);
        if (fuse_alar) {
            float al = v0.x * asS[c0]     + v0.y * asS[c0 + 1] + v0.z * asS[c0 + 2] + v0.w * asS[c0 + 3]
                     + v1.x * asS[c0 + 4] + v1.y * asS[c0 + 5] + v1.z * asS[c0 + 6] + v1.w * asS[c0 + 7];
            float ar = v0.x * adS[c0]     + v0.y * adS[c0 + 1] + v0.z * adS[c0 + 2] + v0.w * adS[c0 + 3]
                     + v1.x * adS[c0 + 4] + v1.y * adS[c0 + 5] + v1.z * adS[c0 + 6] + v1.w * adS[c0 + 7];
            #pragma unroll
            for (int off = 8; off; off >>= 1) {
                al += __shfl_down_sync(0xffffffffu, al, off, 16);
                ar += __shfl_down_sync(0xffffffffu, ar, off, 16);
            }
            if (lane16 == 0 && grow < n) { d_al[grow] = al; d_ar[grow] = ar; }
        }
        __syncthreads();
    }
}

// ---------------- GCN aggregation: warp per node, fp16 gather, fused stats --------------
__global__ __launch_bounds__(256) void gcn_agg_h(const __half* __restrict__ xwh,
                                                 const float* __restrict__ b,
                                                 float* __restrict__ y,
                                                 int do_leaky, int do_stats) {
    int w = threadIdx.x >> 5, lane = threadIdx.x & 31;
    int node = blockIdx.x * 8 + w;
    float4 acc = make_float4(0.f, 0.f, 0.f, 0.f);
    if (node < N_NODES) {
        int s = d_row_ptr[node], e = d_row_ptr[node + 1];
        for (int base = s; base < e; base += 32) {
            int j = base + lane;
            int srcL = 0; float nrmL = 0.f;
            if (j < e) { srcL = d_csr_src[j]; nrmL = d_csr_norm[j]; }
            int cnt = min(32, e - base);
            if (cnt == 32) {
                #pragma unroll 8
                for (int q = 0; q < 32; q++) {
                    int   sq = __shfl_sync(0xffffffffu, srcL, q);
                    float nq = __shfl_sync(0xffffffffu, nrmL, q);
                    uint2 v = ((const uint2*)(xwh + (size_t)sq * CCH))[lane];
                    float2 f01 = __half22float2(*(__half2*)&v.x);
                    float2 f23 = __half22float2(*(__half2*)&v.y);
                    acc.x += nq * f01.x; acc.y += nq * f01.y;
                    acc.z += nq * f23.x; acc.w += nq * f23.y;
                }
            } else {
                for (int q = 0; q < cnt; q++) {
                    int   sq = __shfl_sync(0xffffffffu, srcL, q);
                    float nq = __shfl_sync(0xffffffffu, nrmL, q);
                    uint2 v = ((const uint2*)(xwh + (size_t)sq * CCH))[lane];
                    float2 f01 = __half22float2(*(__half2*)&v.x);
                    float2 f23 = __half22float2(*(__half2*)&v.y);
                    acc.x += nq * f01.x; acc.y += nq * f01.y;
                    acc.z += nq * f23.x; acc.w += nq * f23.y;
                }
            }
        }
        float4 bb = ((const float4*)b)[lane];
        acc.x += bb.x; acc.y += bb.y; acc.z += bb.z; acc.w += bb.w;
        if (do_leaky) {
            acc.x = leaky01(acc.x); acc.y = leaky01(acc.y);
            acc.z = leaky01(acc.z); acc.w = leaky01(acc.w);
        }
        ((float4*)(y + (size_t)node * CCH))[lane] = acc;
    }
    if (do_stats) {
        __shared__ float4 ssum[8][32], ssq[8][32];
        ssum[w][lane] = acc;
        ssq[w][lane]  = make_float4(acc.x * acc.x, acc.y * acc.y, acc.z * acc.z, acc.w * acc.w);
        __syncthreads();
        if (w == 0) {
            float4 s = ssum[0][lane], q = ssq[0][lane];
            #pragma unroll
            for (int i = 1; i < 8; i++) {
                float4 a = ssum[i][lane], p = ssq[i][lane];
                s.x += a.x; s.y += a.y; s.z += a.z; s.w += a.w;
                q.x += p.x; q.y += p.y; q.z += p.z; q.w += p.w;
            }
            int c = lane * 4;
            atomicAdd(&d_stat[c + 0], s.x); atomicAdd(&d_stat[c + 1], s.y);
            atomicAdd(&d_stat[c + 2], s.z); atomicAdd(&d_stat[c + 3], s.w);
            atomicAdd(&d_stat[CCH + c + 0], q.x); atomicAdd(&d_stat[CCH + c + 1], q.y);
            atomicAdd(&d_stat[CCH + c + 2], q.z); atomicAdd(&d_stat[CCH + c + 3], q.w);
        }
    }
}

// ---------------- GAT aggregation: 2 edge passes (max; fused exp+denom+gather) --------
__global__ __launch_bounds__(256) void gat_agg_h(const __half* __restrict__ xwh,
                                                 const float* __restrict__ b,
                                                 float* __restrict__ y) {
    int w = threadIdx.x >> 5, lane = threadIdx.x & 31;
    int node = blockIdx.x * 8 + w;
    float4 acc = make_float4(0.f, 0.f, 0.f, 0.f);
    if (node < N_NODES) {
        int s = d_row_ptr[node], e = d_row_ptr[node + 1];
        float arn = d_ar[node];

        float m = -1e30f;
        for (int j = s + lane; j < e; j += 32)
            m = fmaxf(m, leaky20(d_al[d_csr_src[j]] + arn));
        #pragma unroll
        for (int off = 16; off; off >>= 1) m = fmaxf(m, __shfl_xor_sync(0xffffffffu, m, off));

        // fused pass: unnormalized exp weights, denominator, feature gather
        float denom = 0.f;
        for (int base = s; base < e; base += 32) {
            int j = base + lane;
            int srcL = 0; float exL = 0.f;
            if (j < e) {
                srcL = d_csr_src[j];
                exL = __expf(leaky20(d_al[srcL] + arn) - m);
                denom += exL;
            }
            int cnt = min(32, e - base);
            if (cnt == 32) {
                #pragma unroll 8
                for (int q = 0; q < 32; q++) {
                    int   sq = __shfl_sync(0xffffffffu, srcL, q);
                    float aq = __shfl_sync(0xffffffffu, exL, q);
                    uint2 v = ((const uint2*)(xwh + (size_t)sq * CCH))[lane];
                    float2 f01 = __half22float2(*(__half2*)&v.x);
                    float2 f23 = __half22float2(*(__half2*)&v.y);
                    acc.x += aq * f01.x; acc.y += aq * f01.y;
                    acc.z += aq * f23.x; acc.w += aq * f23.y;
                }
            } else {
                for (int q = 0; q < cnt; q++) {
                    int   sq = __shfl_sync(0xffffffffu, srcL, q);
                    float aq = __shfl_sync(0xffffffffu, exL, q);
                    uint2 v = ((const uint2*)(xwh + (size_t)sq * CCH))[lane];
                    float2 f01 = __half22float2(*(__half2*)&v.x);
                    float2 f23 = __half22float2(*(__half2*)&v.y);
                    acc.x += aq * f01.x; acc.y += aq * f01.y;
                    acc.z += aq * f23.x; acc.w += aq * f23.y;
                }
            }
        }
        #pragma unroll
        for (int off = 16; off; off >>= 1) denom += __shfl_xor_sync(0xffffffffu, denom, off);
        float inv = 1.f / denom;

        float4 bb = ((const float4*)b)[lane];
        acc.x = acc.x * inv + bb.x; acc.y = acc.y * inv + bb.y;
        acc.z = acc.z * inv + bb.z; acc.w = acc.w * inv + bb.w;
        ((float4*)(y + (size_t)node * CCH))[lane] = acc;
    } else {
        acc = make_float4(0.f, 0.f, 0.f, 0.f);
    }
    // fused GraphNorm stats
    __shared__ float4 ssum[8][32], ssq[8][32];
    ssum[w][lane] = acc;
    ssq[w][lane]  = make_float4(acc.x * acc.x, acc.y * acc.y, acc.z * acc.z, acc.w * acc.w);
    __syncthreads();
    if (w == 0) {
        float4 s = ssum[0][lane], q = ssq[0][lane];
        #pragma unroll
        for (int i = 1; i < 8; i++) {
            float4 a = ssum[i][lane], p = ssq[i][lane];
            s.x += a.x; s.y += a.y; s.z += a.z; s.w += a.w;
            q.x += p.x; q.y += p.y; q.z += p.z; q.w += p.w;
        }
        int c = lane * 4;
        atomicAdd(&d_stat[c + 0], s.x); atomicAdd(&d_stat[c + 1], s.y);
        atomicAdd(&d_stat[c + 2], s.z); atomicAdd(&d_stat[c + 3], s.w);
        atomicAdd(&d_stat[CCH + c + 0], q.x); atomicAdd(&d_stat[CCH + c + 1], q.y);
        atomicAdd(&d_stat[CCH + c + 2], q.z); atomicAdd(&d_stat[CCH + c + 3], q.w);
    }
}

// ---------------- GraphNorm finalize ----------------
__global__ void norm_final(const float* __restrict__ alpha) {
    int c = threadIdx.x;
    float m = d_stat[c] * (1.0f / N_NODES);
    float q = d_stat[CCH + c] * (1.0f / N_NODES);
    float a = alpha[c];
    float var = q - (2.f * a - a * a) * m * m;   // E[(y - a*mean)^2]
    d_shift[c] = a * m;
    d_rstd[c]  = rsqrtf(var + 1e-5f);
    d_stat[c] = 0.f;            // reset for next layer
    d_stat[CCH + c] = 0.f;
}

// ---------------- output head ----------------
// fused: final norm_apply (no write-back needed) + dot with Wout
__global__ void gemv_out_f(const float* __restrict__ x, const float* __restrict__ yin,
                           const float* __restrict__ gamma, const float* __restrict__ beta,
                           const float* __restrict__ Wout) {
    int g = blockIdx.x * blockDim.x + threadIdx.x;
    int node = g >> 5, lane = g & 31;
    if (node >= N_NODES) return;
    float4 xv = ((const float4*)(x + (size_t)node * CCH))[lane];
    float4 yv = ((const float4*)(yin + (size_t)node * CCH))[lane];
    float4 gm = ((const float4*)gamma)[lane];
    float4 bt = ((const float4*)beta)[lane];
    float4 sh = ((const float4*)d_shift)[lane];
    float4 rs = ((const float4*)d_rstd)[lane];
    float4 w  = ((const float4*)Wout)[lane];
    float vx = xv.x + leaky01(gm.x * (yv.x - sh.x) * rs.x + bt.x);
    float vy = xv.y + leaky01(gm.y * (yv.y - sh.y) * rs.y + bt.y);
    float vz = xv.z + leaky01(gm.z * (yv.z - sh.z) * rs.z + bt.z);
    float vw = xv.w + leaky01(gm.w * (yv.w - sh.w) * rs.w + bt.w);
    float d = vx * w.x + vy * w.y + vz * w.z + vw * w.w;
    #pragma unroll
    for (int off = 16; off; off >>= 1) d += __shfl_down_sync(0xffffffffu, d, off);
    if (lane == 0) d_xw1[node] = d;
}

__global__ void scalar_agg(const float* __restrict__ b_out) {
    int g = blockIdx.x * blockDim.x + threadIdx.x;
    int node = g >> 5, lane = g & 31;
    if (node >= N_NODES) return;
    int s = d_row_ptr[node], e = d_row_ptr[node + 1];
    float acc = 0.f;
    for (int j = s + lane; j < e; j += 32)
        acc += d_csr_norm[j] * d_xw1[d_csr_src[j]];
    #pragma unroll
    for (int off = 16; off; off >>= 1) acc += __shfl_down_sync(0xffffffffu, acc, off);
    if (lane == 0) d_xs[node] = leaky01(acc + b_out[0]);
}

__global__ void fc1_partial(const float* __restrict__ W1) {
    int c = threadIdx.x;
    float acc = 0.f;
    for (int n = blockIdx.x; n < N_NODES; n += gridDim.x)
        acc += d_xs[n] * W1[(size_t)n * CCH + c];
    atomicAdd(&d_hraw[c], acc);
}

__global__ void fc1_final(const float* __restrict__ b1) {
    int c = threadIdx.x;
    float v = d_hraw[c] + b1[c];
    d_h[c] = v > 0.f ? v : 0.f;
}

__global__ void fc2_k(const float* __restrict__ W2, const float* __restrict__ b2,
                      float* __restrict__ out) {
    __shared__ float hs[CCH];
    int tid = threadIdx.x;
    hs[tid] = d_h[tid];
    __syncthreads();
    int p = blockIdx.x * 128 + tid;
    if (p >= POI_LEN_) return;
    float acc = b2[p];
    #pragma unroll 8
    for (int j = 0; j < CCH; j++)
        acc += hs[j] * W2[(size_t)j * POI_LEN_ + p];
    out[p] = acc > 0.f ? acc : 0.f;
}

// ---------------- launch ----------------
static inline int div_up(int a, int b) { return (a + b - 1) / b; }

extern "C" void kernel_launch(void* const* d_in, const int* in_sizes, int n_in,
                              void* d_out, int out_size) {
    const int*   poi_ids   = (const int*)  d_in[0];
    const int*   cat_ids   = (const int*)  d_in[1];
    const float* feat3     = (const float*)d_in[2];
    const int*   edge_index= (const int*)  d_in[3];
    const float* edge_w    = (const float*)d_in[4];
    const float* poi_emb   = (const float*)d_in[5];
    const float* cat_emb   = (const float*)d_in[6];
    const float* Win       = (const float*)d_in[7];
    const float* b_in      = (const float*)d_in[8];
    const float* gcn_W     = (const float*)d_in[9];
    const float* gcn_b     = (const float*)d_in[10];
    const float* gn_gamma  = (const float*)d_in[11];
    const float* gn_beta   = (const float*)d_in[12];
    const float* gn_alpha  = (const float*)d_in[13];
    const float* gat_W     = (const float*)d_in[14];
    const float* gat_asrc  = (const float*)d_in[15];
    const float* gat_adst  = (const float*)d_in[16];
    const float* gat_b     = (const float*)d_in[17];
    const float* Wout      = (const float*)d_in[18];
    const float* b_out     = (const float*)d_in[19];
    const float* fc_W1     = (const float*)d_in[20];
    const float* fc_b1     = (const float*)d_in[21];
    const float* fc_W2     = (const float*)d_in[22];
    const float* fc_b2     = (const float*)d_in[23];
    float* out = (float*)d_out;

    float *feat_p, *x_p, *y_p; __half *xwh_p;
    cudaGetSymbolAddress((void**)&feat_p, d_feat);
    cudaGetSymbolAddress((void**)&x_p,  d_x);
    cudaGetSymbolAddress((void**)&y_p,  d_y);
    cudaGetSymbolAddress((void**)&xwh_p, d_xwh);

    const int warpGrid = div_up(N_NODES * 32, 256);
    const int edgeGrid = div_up(NEDGES, 256);
    const int gemmGrid = N_PAD / GM;             // 600
    const int aggGrid  = div_up(N_NODES, 8);

    // CSR build
    init_k<<<div_up(N_NODES, 256), 256>>>();
    hist_k<<<edgeGrid, 256>>>(edge_index);
    scan_k<<<1, 1024>>>();
    selfloop_k<<<div_up(N_NODES, 256), 256>>>();
    scatter_k<<<edgeGrid, 256>>>(edge_index, edge_w);
    deg_k<<<warpGrid, 256>>>();
    csnorm_k<<<warpGrid, 256>>>();

    // features + input conv
    feat_k<<<N_NODES, 128>>>(poi_ids, cat_ids, feat3, poi_emb, cat_emb);
    gemm_tf32_v3<<<gemmGrid, 256>>>(feat_p, Win, xwh_p, N_NODES, FEAT_DIM,
                                    nullptr, nullptr, nullptr, nullptr, 0,
                                    nullptr, nullptr, 0);
    gcn_agg_h<<<aggGrid, 256>>>(xwh_p, b_in, x_p, 1, 0);

    for (int l = 0; l < NLAYERS; l++) {
        // GCN half: gemm (with previous GAT norm fused for l>0), agg + stats, finalize
        if (l == 0)
            gemm_tf32_v3<<<gemmGrid, 256>>>(x_p, gcn_W, xwh_p, N_NODES, CCH,
                                            nullptr, nullptr, nullptr, nullptr, 0,
                                            nullptr, nullptr, 0);
        else
            gemm_tf32_v3<<<gemmGrid, 256>>>(nullptr, gcn_W + l * CCH * CCH, xwh_p, N_NODES, CCH,
                                            y_p, x_p,
                                            gn_gamma + (l - 1) * CCH, gn_beta + (l - 1) * CCH, 1,
                                            nullptr, nullptr, 0);
        gcn_agg_h<<<aggGrid, 256>>>(xwh_p, gcn_b + l * CCH, y_p, 0, 1);
        norm_final<<<1, 128>>>(gn_alpha + l * CCH);

        // GAT half: gemm with fused GCN-norm + alar epilogue, agg + stats, finalize
        gemm_tf32_v3<<<gemmGrid, 256>>>(nullptr, gat_W + l * CCH * CCH, xwh_p, N_NODES, CCH,
                                        y_p, x_p,
                                        gn_gamma + l * CCH, gn_beta + l * CCH, 1,
                                        gat_asrc + l * CCH, gat_adst + l * CCH, 1);
        gat_agg_h<<<aggGrid, 256>>>(xwh_p, gat_b + l * CCH, y_p);
        norm_final<<<1, 128>>>(gn_alpha + l * CCH);
    }

    // output conv (final norm fused) + FC head
    gemv_out_f<<<warpGrid, 256>>>(x_p, y_p, gn_gamma + 4 * CCH, gn_beta + 4 * CCH, Wout);
    scalar_agg<<<warpGrid, 256>>>(b_out);
    fc1_partial<<<592, 128>>>(fc_W1);
    fc1_final<<<1, 128>>>(fc_b1);
    fc2_k<<<div_up(POI_LEN_, 128), 128>>>(fc_W2, fc_b2, out);
}

// round 5
// speedup vs baseline: 2.0542x; 2.0004x over previous
#include <cuda_runtime.h>
#include <cuda_fp16.h>
#include <mma.h>
#include <math.h>

using namespace nvcuda;

#define N_NODES 38332
#define N_PAD   38400
#define POI_LEN_ 38333
#define POI_DIM 300
#define CAT_DIM 100
#define FEAT_DIM 403
#define CCH 128
#define NLAYERS 5
#define NEDGES 1200000
#define TOTE (NEDGES + N_NODES)
#define NEG 0.01f
#define GAT_NEG 0.2f

// ---------------- scratch (static __device__, no allocation) ----------------
__device__ float  d_feat[N_NODES * FEAT_DIM];
__device__ float  d_x [N_NODES * CCH];
__device__ float  d_xw[N_PAD * CCH];
__device__ __half d_xwh[N_PAD * CCH];
__device__ float  d_y [N_NODES * CCH];
__device__ int    d_csr_src [TOTE];
__device__ float  d_csr_w   [TOTE];
__device__ float  d_csr_norm[TOTE];
__device__ int    d_row_ptr[N_NODES + 1];
__device__ int    d_cnt   [N_NODES];
__device__ int    d_cursor[N_NODES];
__device__ float  d_dinv[N_NODES];
__device__ float  d_al [N_NODES];
__device__ float  d_ar [N_NODES];
__device__ float  d_xw1[N_NODES];
__device__ float  d_xs [N_NODES];
__device__ float  d_stat[2 * CCH];
__device__ float  d_shift[CCH];
__device__ float  d_rstd [CCH];
__device__ float  d_hraw[CCH];
__device__ float  d_h   [CCH];

__device__ __forceinline__ float leaky01(float v) { return v > 0.f ? v : NEG * v; }
__device__ __forceinline__ float leaky20(float v) { return v > 0.f ? v : GAT_NEG * v; }

// spill-proof half4 -> float4 conversion (no pointer punning on registers)
__device__ __forceinline__ float4 h4_to_f4(uint2 u) {
    float4 r;
    asm("{\n\t"
        ".reg .b16 a, b, c, d;\n\t"
        "mov.b32 {a, b}, %4;\n\t"
        "mov.b32 {c, d}, %5;\n\t"
        "cvt.f32.f16 %0, a;\n\t"
        "cvt.f32.f16 %1, b;\n\t"
        "cvt.f32.f16 %2, c;\n\t"
        "cvt.f32.f16 %3, d;\n\t"
        "}"
        : "=f"(r.x), "=f"(r.y), "=f"(r.z), "=f"(r.w)
        : "r"(u.x), "r"(u.y));
    return r;
}

// ---------------- CSR build ----------------
__global__ void init_k() {
    int i = blockIdx.x * blockDim.x + threadIdx.x;
    if (i < N_NODES) d_cnt[i] = 1;                 // self-loop pre-counted
    if (i < CCH)     d_hraw[i] = 0.f;
    if (i < 2 * CCH) d_stat[i] = 0.f;
}

__global__ void hist_k(const int* __restrict__ ei) {
    int e = blockIdx.x * blockDim.x + threadIdx.x;
    if (e < NEDGES) atomicAdd(&d_cnt[ei[NEDGES + e]], 1);   // dst row
}

__global__ void scan_k() {
    const int T = 1024;
    const int ITEMS = (N_NODES + T - 1) / T;   // 38
    int tid = threadIdx.x;
    int start = tid * ITEMS;
    int end   = min(start + ITEMS, N_NODES);
    int s = 0;
    for (int i = start; i < end; i++) s += d_cnt[i];
    __shared__ int ps[T];
    ps[tid] = s; __syncthreads();
    for (int off = 1; off < T; off <<= 1) {
        int v = (tid >= off) ? ps[tid - off] : 0;
        __syncthreads();
        ps[tid] += v;
        __syncthreads();
    }
    int incl = ps[tid];
    int run  = incl - s;                        // exclusive prefix
    for (int i = start; i < end; i++) { d_row_ptr[i] = run; run += d_cnt[i]; }
    if (tid == T - 1) d_row_ptr[N_NODES] = incl;
}

__global__ void selfloop_k() {
    int i = blockIdx.x * blockDim.x + threadIdx.x;
    if (i < N_NODES) {
        int p = d_row_ptr[i];
        d_csr_src[p] = i;
        d_csr_w[p]   = 1.0f;
        d_cursor[i]  = p + 1;
    }
}

__global__ void scatter_k(const int* __restrict__ ei, const float* __restrict__ ew) {
    int e = blockIdx.x * blockDim.x + threadIdx.x;
    if (e < NEDGES) {
        int dst = ei[NEDGES + e];
        int p = atomicAdd(&d_cursor[dst], 1);
        d_csr_src[p] = ei[e];
        d_csr_w[p]   = ew[e];
    }
}

__global__ void deg_k() {
    int g = blockIdx.x * blockDim.x + threadIdx.x;
    int node = g >> 5, lane = g & 31;
    if (node >= N_NODES) return;
    int s = d_row_ptr[node], e = d_row_ptr[node + 1];
    float acc = 0.f;
    for (int j = s + lane; j < e; j += 32) acc += d_csr_w[j];
    #pragma unroll
    for (int off = 16; off; off >>= 1) acc += __shfl_down_sync(0xffffffffu, acc, off);
    if (lane == 0) d_dinv[node] = rsqrtf(acc);   // deg >= 1 (self-loop)
}

__global__ void csnorm_k() {
    int g = blockIdx.x * blockDim.x + threadIdx.x;
    int node = g >> 5, lane = g & 31;
    if (node >= N_NODES) return;
    int s = d_row_ptr[node], e = d_row_ptr[node + 1];
    float dv = d_dinv[node];
    for (int j = s + lane; j < e; j += 32)
        d_csr_norm[j] = d_dinv[d_csr_src[j]] * d_csr_w[j] * dv;
}

// ---------------- feature assembly ----------------
__global__ void feat_k(const int* __restrict__ poi_ids, const int* __restrict__ cat_ids,
                       const float* __restrict__ feat3,
                       const float* __restrict__ poi_emb, const float* __restrict__ cat_emb) {
    int node = blockIdx.x, tid = threadIdx.x;
    int pid = poi_ids[node], cid = cat_ids[node];
    float* f = d_feat + (long)node * FEAT_DIM;
    for (int k = tid; k < POI_DIM; k += 128) f[k] = poi_emb[(long)pid * POI_DIM + k];
    for (int k = tid; k < CAT_DIM; k += 128) f[POI_DIM + k] = cat_emb[cid * CAT_DIM + k];
    if (tid < 3) f[400 + tid] = feat3[node * 3 + tid];
}

// ---------------- GEMM (tf32 tensor cores): Y[n,128] = X[n,K] @ W[K,128] ----------------
// EXACT R2 kernel (known-good 1409us configuration).
#define GM 64
#define GN 128
#define GK 16

__global__ __launch_bounds__(256) void gemm_tf32(const float* __restrict__ X,
                                                 const float* __restrict__ W,
                                                 float* __restrict__ Y, int n, int K) {
    __shared__ __align__(16) float Xs[GM][GK];
    __shared__ __align__(16) float Ws[GK][GN];
    int tid = threadIdx.x;
    int warp = tid >> 5;
    int wm = warp & 1;       // row group (32 rows)
    int wn = warp >> 1;      // col group (32 cols)
    int row0 = blockIdx.x * GM;

    wmma::fragment<wmma::accumulator, 16, 16, 8, float> c[2][2];
    #pragma unroll
    for (int i = 0; i < 2; i++)
        #pragma unroll
        for (int j = 0; j < 2; j++) wmma::fill_fragment(c[i][j], 0.f);

    for (int k0 = 0; k0 < K; k0 += GK) {
        #pragma unroll
        for (int i = 0; i < 4; i++) {
            int e = tid + i * 256;
            int r = e >> 4, kk = e & 15;
            int gr = row0 + r, gk = k0 + kk;
            Xs[r][kk] = (gr < n && gk < K) ? X[(long)gr * K + gk] : 0.f;
        }
        #pragma unroll
        for (int i = 0; i < 2; i++) {
            int e = tid + i * 256;
            int kk = e >> 5, c4 = e & 31;
            int gk = k0 + kk;
            float4 v = (gk < K) ? ((const float4*)(W + (long)gk * GN))[c4]
                                : make_float4(0.f, 0.f, 0.f, 0.f);
            ((float4*)&Ws[kk][0])[c4] = v;
        }
        __syncthreads();
        #pragma unroll
        for (int ks = 0; ks < 2; ks++) {
            wmma::fragment<wmma::matrix_a, 16, 16, 8, wmma::precision::tf32, wmma::row_major> a[2];
            wmma::fragment<wmma::matrix_b, 16, 16, 8, wmma::precision::tf32, wmma::row_major> bf[2];
            #pragma unroll
            for (int i = 0; i < 2; i++) {
                wmma::load_matrix_sync(a[i], &Xs[wm * 32 + i * 16][ks * 8], GK);
                #pragma unroll
                for (int t = 0; t < a[i].num_elements; t++)
                    a[i].x[t] = wmma::__float_to_tf32(a[i].x[t]);
            }
            #pragma unroll
            for (int j = 0; j < 2; j++) {
                wmma::load_matrix_sync(bf[j], &Ws[ks * 8][wn * 32 + j * 16], GN);
                #pragma unroll
                for (int t = 0; t < bf[j].num_elements; t++)
                    bf[j].x[t] = wmma::__float_to_tf32(bf[j].x[t]);
            }
            #pragma unroll
            for (int i = 0; i < 2; i++)
                #pragma unroll
                for (int j = 0; j < 2; j++)
                    wmma::mma_sync(c[i][j], a[i], bf[j], c[i][j]);
        }
        __syncthreads();
    }
    #pragma unroll
    for (int i = 0; i < 2; i++)
        #pragma unroll
        for (int j = 0; j < 2; j++)
            wmma::store_matrix_sync(Y + (long)(row0 + wm * 32 + i * 16) * GN + wn * 32 + j * 16,
                                    c[i][j], GN, wmma::mem_row_major);
}

// ---------------- fp32 -> fp16 convert (the ONLY new stage vs R2) ----------------
__global__ void x2h_k(const float* __restrict__ xw, __half* __restrict__ xwh) {
    int idx = blockIdx.x * blockDim.x + threadIdx.x;       // float4 group
    if (idx >= N_NODES * CCH / 4) return;
    float4 v = ((const float4*)xw)[idx];
    __half2* o = (__half2*)xwh;
    o[2 * idx]     = __floats2half2_rn(v.x, v.y);
    o[2 * idx + 1] = __floats2half2_rn(v.z, v.w);
}

// ---------------- GCN aggregation: warp per node, fp16 gather ----------------
__global__ __launch_bounds__(256) void gcn_agg_h2(const __half* __restrict__ xwh,
                                                  const float* __restrict__ b,
                                                  float* __restrict__ y, int do_leaky) {
    int node = (blockIdx.x * blockDim.x + threadIdx.x) >> 5;
    int lane = threadIdx.x & 31;
    if (node >= N_NODES) return;
    int s = d_row_ptr[node], e = d_row_ptr[node + 1];
    float4 acc = make_float4(0.f, 0.f, 0.f, 0.f);
    for (int base = s; base < e; base += 32) {
        int j = base + lane;
        int srcL = 0; float nrmL = 0.f;
        if (j < e) { srcL = d_csr_src[j]; nrmL = d_csr_norm[j]; }
        int cnt = min(32, e - base);
        for (int q = 0; q < cnt; q++) {
            int   sq = __shfl_sync(0xffffffffu, srcL, q);
            float nq = __shfl_sync(0xffffffffu, nrmL, q);
            uint2 u = ((const uint2*)(xwh + (size_t)sq * CCH))[lane];
            float4 v = h4_to_f4(u);
            acc.x += nq * v.x; acc.y += nq * v.y;
            acc.z += nq * v.z; acc.w += nq * v.w;
        }
    }
    float4 bb = ((const float4*)b)[lane];
    acc.x += bb.x; acc.y += bb.y; acc.z += bb.z; acc.w += bb.w;
    if (do_leaky) {
        acc.x = leaky01(acc.x); acc.y = leaky01(acc.y);
        acc.z = leaky01(acc.z); acc.w = leaky01(acc.w);
    }
    ((float4*)(y + (size_t)node * CCH))[lane] = acc;
}

// ---------------- GAT: al/ar (verbatim R2, reads fp32 xw) ----------------
__global__ void alar_k(const float* __restrict__ xw, const float* __restrict__ asrc,
                       const float* __restrict__ adst) {
    int g = blockIdx.x * blockDim.x + threadIdx.x;
    int node = g >> 5, lane = g & 31;
    if (node >= N_NODES) return;
    float4 v = ((const float4*)(xw + (long)node * CCH))[lane];
    float4 a = ((const float4*)asrc)[lane];
    float4 d = ((const float4*)adst)[lane];
    float dl = v.x * a.x + v.y * a.y + v.z * a.z + v.w * a.w;
    float dr = v.x * d.x + v.y * d.y + v.z * d.z + v.w * d.w;
    #pragma unroll
    for (int off = 16; off; off >>= 1) {
        dl += __shfl_down_sync(0xffffffffu, dl, off);
        dr += __shfl_down_sync(0xffffffffu, dr, off);
    }
    if (lane == 0) { d_al[node] = dl; d_ar[node] = dr; }
}

// ---------------- GAT aggregation: warp per node, fp16 gather, 2 edge passes -------
__global__ __launch_bounds__(256) void gat_agg_h2(const __half* __restrict__ xwh,
                                                  const float* __restrict__ b,
                                                  float* __restrict__ y) {
    int node = (blockIdx.x * blockDim.x + threadIdx.x) >> 5;
    int lane = threadIdx.x & 31;
    if (node >= N_NODES) return;
    int s = d_row_ptr[node], e = d_row_ptr[node + 1];
    float arn = d_ar[node];

    float m = -1e30f;
    for (int j = s + lane; j < e; j += 32)
        m = fmaxf(m, leaky20(d_al[d_csr_src[j]] + arn));
    #pragma unroll
    for (int off = 16; off; off >>= 1) m = fmaxf(m, __shfl_xor_sync(0xffffffffu, m, off));

    // fused: unnormalized exp weights + denominator + gather
    float denom = 0.f;
    float4 acc = make_float4(0.f, 0.f, 0.f, 0.f);
    for (int base = s; base < e; base += 32) {
        int j = base + lane;
        int srcL = 0; float exL = 0.f;
        if (j < e) {
            srcL = d_csr_src[j];
            exL = __expf(leaky20(d_al[srcL] + arn) - m);
            denom += exL;
        }
        int cnt = min(32, e - base);
        for (int q = 0; q < cnt; q++) {
            int   sq = __shfl_sync(0xffffffffu, srcL, q);
            float aq = __shfl_sync(0xffffffffu, exL, q);
            uint2 u = ((const uint2*)(xwh + (size_t)sq * CCH))[lane];
            float4 v = h4_to_f4(u);
            acc.x += aq * v.x; acc.y += aq * v.y;
            acc.z += aq * v.z; acc.w += aq * v.w;
        }
    }
    #pragma unroll
    for (int off = 16; off; off >>= 1) denom += __shfl_xor_sync(0xffffffffu, denom, off);
    float inv = 1.f / denom;

    float4 bb = ((const float4*)b)[lane];
    ((float4*)(y + (size_t)node * CCH))[lane] =
        make_float4(acc.x * inv + bb.x, acc.y * inv + bb.y,
                    acc.z * inv + bb.z, acc.w * inv + bb.w);
}

// ---------------- GraphNorm (verbatim R2, + reset folded into finalize) ----------------
__global__ void norm_reduce(const float* __restrict__ y) {
    int c = threadIdx.x;
    float ls = 0.f, lq = 0.f;
    for (int n = blockIdx.x; n < N_NODES; n += gridDim.x) {
        float v = y[(long)n * CCH + c];
        ls += v; lq += v * v;
    }
    atomicAdd(&d_stat[c], ls);
    atomicAdd(&d_stat[CCH + c], lq);
}

__global__ void norm_final(const float* __restrict__ alpha) {
    int c = threadIdx.x;
    float m = d_stat[c] * (1.0f / N_NODES);
    float q = d_stat[CCH + c] * (1.0f / N_NODES);
    float a = alpha[c];
    float var = q - (2.f * a - a * a) * m * m;   // E[(y - a*mean)^2]
    d_shift[c] = a * m;
    d_rstd[c]  = rsqrtf(var + 1e-5f);
    d_stat[c] = 0.f;
    d_stat[CCH + c] = 0.f;
}

__global__ void norm_apply(const float* __restrict__ y, float* __restrict__ x,
                           const float* __restrict__ gamma, const float* __restrict__ beta) {
    int idx = blockIdx.x * blockDim.x + threadIdx.x;
    if (idx >= N_NODES * CCH) return;
    int c = idx & (CCH - 1);
    float t = gamma[c] * (y[idx] - d_shift[c]) * d_rstd[c] + beta[c];
    x[idx] += leaky01(t);
}

// ---------------- output head (verbatim R2) ----------------
__global__ void gemv_out(const float* __restrict__ x, const float* __restrict__ Wout) {
    int g = blockIdx.x * blockDim.x + threadIdx.x;
    int node = g >> 5, lane = g & 31;
    if (node >= N_NODES) return;
    float4 v = ((const float4*)(x + (long)node * CCH))[lane];
    float4 w = ((const float4*)Wout)[lane];
    float d = v.x * w.x + v.y * w.y + v.z * w.z + v.w * w.w;
    #pragma unroll
    for (int off = 16; off; off >>= 1) d += __shfl_down_sync(0xffffffffu, d, off);
    if (lane == 0) d_xw1[node] = d;
}

__global__ void scalar_agg(const float* __restrict__ b_out) {
    int g = blockIdx.x * blockDim.x + threadIdx.x;
    int node = g >> 5, lane = g & 31;
    if (node >= N_NODES) return;
    int s = d_row_ptr[node], e = d_row_ptr[node + 1];
    float acc = 0.f;
    for (int j = s + lane; j < e; j += 32)
        acc += d_csr_norm[j] * d_xw1[d_csr_src[j]];
    #pragma unroll
    for (int off = 16; off; off >>= 1) acc += __shfl_down_sync(0xffffffffu, acc, off);
    if (lane == 0) d_xs[node] = leaky01(acc + b_out[0]);
}

__global__ void fc1_partial(const float* __restrict__ W1) {
    int c = threadIdx.x;
    float acc = 0.f;
    for (int n = blockIdx.x; n < N_NODES; n += gridDim.x)
        acc += d_xs[n] * W1[(long)n * CCH + c];
    atomicAdd(&d_hraw[c], acc);
}

__global__ void fc1_final(const float* __restrict__ b1) {
    int c = threadIdx.x;
    float v = d_hraw[c] + b1[c];
    d_h[c] = v > 0.f ? v : 0.f;
}

__global__ void fc2_k(const float* __restrict__ W2, const float* __restrict__ b2,
                      float* __restrict__ out) {
    __shared__ float hs[CCH];
    int tid = threadIdx.x;
    hs[tid] = d_h[tid];
    __syncthreads();
    int p = blockIdx.x * 128 + tid;
    if (p >= POI_LEN_) return;
    float acc = b2[p];
    #pragma unroll 8
    for (int j = 0; j < CCH; j++)
        acc += hs[j] * W2[(long)j * POI_LEN_ + p];
    out[p] = acc > 0.f ? acc : 0.f;
}

// ---------------- launch ----------------
static inline int div_up(int a, int b) { return (a + b - 1) / b; }

extern "C" void kernel_launch(void* const* d_in, const int* in_sizes, int n_in,
                              void* d_out, int out_size) {
    const int*   poi_ids   = (const int*)  d_in[0];
    const int*   cat_ids   = (const int*)  d_in[1];
    const float* feat3     = (const float*)d_in[2];
    const int*   edge_index= (const int*)  d_in[3];
    const float* edge_w    = (const float*)d_in[4];
    const float* poi_emb   = (const float*)d_in[5];
    const float* cat_emb   = (const float*)d_in[6];
    const float* Win       = (const float*)d_in[7];
    const float* b_in      = (const float*)d_in[8];
    const float* gcn_W     = (const float*)d_in[9];
    const float* gcn_b     = (const float*)d_in[10];
    const float* gn_gamma  = (const float*)d_in[11];
    const float* gn_beta   = (const float*)d_in[12];
    const float* gn_alpha  = (const float*)d_in[13];
    const float* gat_W     = (const float*)d_in[14];
    const float* gat_asrc  = (const float*)d_in[15];
    const float* gat_adst  = (const float*)d_in[16];
    const float* gat_b     = (const float*)d_in[17];
    const float* Wout      = (const float*)d_in[18];
    const float* b_out     = (const float*)d_in[19];
    const float* fc_W1     = (const float*)d_in[20];
    const float* fc_b1     = (const float*)d_in[21];
    const float* fc_W2     = (const float*)d_in[22];
    const float* fc_b2     = (const float*)d_in[23];
    float* out = (float*)d_out;

    float *feat_p, *x_p, *xw_p, *y_p; __half *xwh_p;
    cudaGetSymbolAddress((void**)&feat_p, d_feat);
    cudaGetSymbolAddress((void**)&x_p,  d_x);
    cudaGetSymbolAddress((void**)&xw_p, d_xw);
    cudaGetSymbolAddress((void**)&y_p,  d_y);
    cudaGetSymbolAddress((void**)&xwh_p, d_xwh);

    const int warpGrid = div_up(N_NODES * 32, 256);
    const int edgeGrid = div_up(NEDGES, 256);
    const int gemmGrid = div_up(N_NODES, GM);
    const int aggGrid  = div_up(N_NODES, 8);
    const int cvtGrid  = div_up(N_NODES * CCH / 4, 256);
    const int ewGrid   = div_up(N_NODES * CCH, 256);

    // CSR build
    init_k<<<div_up(N_NODES, 256), 256>>>();
    hist_k<<<edgeGrid, 256>>>(edge_index);
    scan_k<<<1, 1024>>>();
    selfloop_k<<<div_up(N_NODES, 256), 256>>>();
    scatter_k<<<edgeGrid, 256>>>(edge_index, edge_w);
    deg_k<<<warpGrid, 256>>>();
    csnorm_k<<<warpGrid, 256>>>();

    // features + input conv
    feat_k<<<N_NODES, 128>>>(poi_ids, cat_ids, feat3, poi_emb, cat_emb);
    gemm_tf32<<<gemmGrid, 256>>>(feat_p, Win, xw_p, N_NODES, FEAT_DIM);
    x2h_k<<<cvtGrid, 256>>>(xw_p, xwh_p);
    gcn_agg_h2<<<aggGrid, 256>>>(xwh_p, b_in, x_p, 1);

    for (int l = 0; l < NLAYERS; l++) {
        // GCN unit half
        gemm_tf32<<<gemmGrid, 256>>>(x_p, gcn_W + l * CCH * CCH, xw_p, N_NODES, CCH);
        x2h_k<<<cvtGrid, 256>>>(xw_p, xwh_p);
        gcn_agg_h2<<<aggGrid, 256>>>(xwh_p, gcn_b + l * CCH, y_p, 0);
        norm_reduce<<<592, 128>>>(y_p);
        norm_final<<<1, 128>>>(gn_alpha + l * CCH);
        norm_apply<<<ewGrid, 256>>>(y_p, x_p, gn_gamma + l * CCH, gn_beta + l * CCH);

        // GAT unit half
        gemm_tf32<<<gemmGrid, 256>>>(x_p, gat_W + l * CCH * CCH, xw_p, N_NODES, CCH);
        x2h_k<<<cvtGrid, 256>>>(xw_p, xwh_p);
        alar_k<<<warpGrid, 256>>>(xw_p, gat_asrc + l * CCH, gat_adst + l * CCH);
        gat_agg_h2<<<aggGrid, 256>>>(xwh_p, gat_b + l * CCH, y_p);
        norm_reduce<<<592, 128>>>(y_p);
        norm_final<<<1, 128>>>(gn_alpha + l * CCH);
        norm_apply<<<ewGrid, 256>>>(y_p, x_p, gn_gamma + l * CCH, gn_beta + l * CCH);
    }

    // output conv + FC head
    gemv_out<<<warpGrid, 256>>>(x_p, Wout);
    scalar_agg<<<warpGrid, 256>>>(b_out);
    fc1_partial<<<592, 128>>>(fc_W1);
    fc1_final<<<1, 128>>>(fc_b1);
    fc2_k<<<div_up(POI_LEN_, 128), 128>>>(fc_W2, fc_b2, out);
}